// round 15
// baseline (speedup 1.0000x reference)
#include <cuda_runtime.h>
#include <cuda_bf16.h>
#include <cuda_fp16.h>
#include <cstdint>

// ---------------- problem constants ----------------
#define Hh   128
#define H2   64                  // half2 / float2 channel pairs
#define Bb   16
#define Nn   1000
#define SFf  20
#define Ee   20000
#define NODE_ROWS (Bb*Nn)        // 16000  = 125*128
#define EDGE_ROWS (Bb*Ee)        // 320000
#define BN_EPS 1e-5f
#define STATS_BLOCKS 256

// smem tile geometry (pad 8 -> conflict-free ldmatrix)
#define TPAD 136
#define TBUF (128*TPAD)
#define SM_GEMM (2*TBUF*2)           // node GEMM: A + single B = 69632 B
#define ETILE 160                    // edge tile rows = 8 nodes
#define EBLOCKS (EDGE_ROWS/ETILE)    // 2000
#define SM_EF ((ETILE+128)*TPAD*2)   // A/Ve buffer + B buffer = 78336 B

// ---------------- scratch (__device__ globals) ----------------
__device__ float g_Ux [NODE_ROWS*Hh];
__device__ float g_Vx [NODE_ROWS*Hh];
__device__ float g_Vxf[NODE_ROWS*Hh];
__device__ float g_Vxt[NODE_ROWS*Hh];
__device__ __half g_e1 [(size_t)EDGE_ROWS*Hh];   // e_tmp
__device__ __half g_e2 [(size_t)EDGE_ROWS*Hh];   // Ue
__device__ __half g_e3 [(size_t)EDGE_ROWS*Hh];   // iUe
__device__ float g_psum[STATS_BLOCKS*Hh];
__device__ float g_psq [STATS_BLOCKS*Hh];
__device__ float g_mean[Hh];
__device__ float g_rstd[Hh];
__device__ float g_pps[(size_t)(Bb*Nn)*Hh];      // node: doubles as x_tmp
__device__ float g_ppq[(size_t)(Bb*Nn)*Hh];

__device__ __half g_wt[7][128*128];   // transposed [n][k], fp16

// ---------------- helpers ----------------
__device__ __forceinline__ uint32_t smem_u32(const void* p) {
    uint32_t a;
    asm("{ .reg .u64 t; cvta.to.shared.u64 t, %1; cvt.u32.u64 %0, t; }" : "=r"(a) : "l"(p));
    return a;
}
__device__ __forceinline__ void ldsm_x4(uint32_t* r, uint32_t addr) {
    asm volatile("ldmatrix.sync.aligned.m8n8.x4.shared.b16 {%0,%1,%2,%3}, [%4];"
                 : "=r"(r[0]), "=r"(r[1]), "=r"(r[2]), "=r"(r[3]) : "r"(addr));
}
__device__ __forceinline__ void mma_f16(float* c, const uint32_t* a, const uint32_t* b) {
    asm volatile("mma.sync.aligned.m16n8k16.row.col.f32.f16.f16.f32 "
                 "{%0,%1,%2,%3}, {%4,%5,%6,%7}, {%8,%9}, {%0,%1,%2,%3};"
                 : "+f"(c[0]), "+f"(c[1]), "+f"(c[2]), "+f"(c[3])
                 : "r"(a[0]), "r"(a[1]), "r"(a[2]), "r"(a[3]), "r"(b[0]), "r"(b[1]));
}

// ---------------- node GEMM: 128-row tile, 2 weights, single B buffer, fp32 out ----------------
__global__ __launch_bounds__(512)
void mma_gemm_node(const float* __restrict__ A,
                   const __half* __restrict__ B0, const float* __restrict__ bias0, float* __restrict__ out0,
                   const __half* __restrict__ B1, const float* __restrict__ bias1, float* __restrict__ out1)
{
    extern __shared__ __half sm[];
    __half* Bs = sm + TBUF;
    const int tid = threadIdx.x;
    const int row0 = blockIdx.x * 128;

    {
        const float4* gA = (const float4*)A + (size_t)row0*32;
        #pragma unroll
        for (int i = 0; i < 8; ++i) {
            int idx = i*512 + tid;
            int r = idx >> 5, c = idx & 31;
            float4 v = gA[idx];
            __align__(8) __half h[4];
            h[0] = __float2half_rn(v.x); h[1] = __float2half_rn(v.y);
            h[2] = __float2half_rn(v.z); h[3] = __float2half_rn(v.w);
            *(uint2*)(sm + r*TPAD + c*4) = *(const uint2*)h;
        }
    }

    const int warp = tid >> 5, lane = tid & 31;
    const int wr = warp >> 2, wc = warp & 3;
    const uint32_t a_sm = smem_u32(sm), b_sm = smem_u32(Bs);
    const int a_row  = wr*32 + (lane & 15);
    const int a_koff = (lane >> 4) * 8;
    const int b_n    = wc*32 + (lane & 7) + ((lane >> 4) & 1)*8;
    const int b_koff = ((lane >> 3) & 1) * 8;
    const int gid = lane >> 2, tg = lane & 3;

    const __half* Bsrc[2] = {B0, B1};
    const float* biases[2] = {bias0, bias1};
    float* outs[2] = {out0, out1};

    #pragma unroll
    for (int w = 0; w < 2; ++w) {
        __syncthreads();
        {
            const uint4* gB = (const uint4*)Bsrc[w];
            #pragma unroll
            for (int i = 0; i < 4; ++i) {
                int idx = i*512 + tid;
                int r = idx >> 4, c = idx & 15;
                *(uint4*)(Bs + r*TPAD + c*8) = gB[idx];
            }
        }
        __syncthreads();

        float acc[2][4][4];
        #pragma unroll
        for (int mt = 0; mt < 2; ++mt)
            #pragma unroll
            for (int nt = 0; nt < 4; ++nt)
                #pragma unroll
                for (int i = 0; i < 4; ++i) acc[mt][nt][i] = 0.f;

        #pragma unroll
        for (int ks = 0; ks < 8; ++ks) {
            const int k0 = ks * 16;
            uint32_t ah[2][4];
            #pragma unroll
            for (int mt = 0; mt < 2; ++mt)
                ldsm_x4(ah[mt], a_sm + (uint32_t)((a_row + mt*16)*TPAD + k0 + a_koff) * 2u);
            uint32_t bh[2][4];
            #pragma unroll
            for (int p = 0; p < 2; ++p)
                ldsm_x4(bh[p], b_sm + (uint32_t)((b_n + p*16)*TPAD + k0 + b_koff) * 2u);
            #pragma unroll
            for (int p = 0; p < 2; ++p)
                #pragma unroll
                for (int mt = 0; mt < 2; ++mt) {
                    mma_f16(acc[mt][2*p  ], ah[mt], bh[p]);
                    mma_f16(acc[mt][2*p+1], ah[mt], bh[p] + 2);
                }
        }

        const float* bias = biases[w];
        float* out = outs[w];
        #pragma unroll
        for (int mt = 0; mt < 2; ++mt)
            #pragma unroll
            for (int nt = 0; nt < 4; ++nt) {
                int col = wc*32 + nt*8 + tg*2;
                float b0 = bias[col], b1 = bias[col+1];
                size_t r0 = (size_t)row0 + wr*32 + mt*16 + gid;
                *(float2*)(out + r0*128 + col)     = make_float2(acc[mt][nt][0] + b0, acc[mt][nt][1] + b1);
                *(float2*)(out + (r0+8)*128 + col) = make_float2(acc[mt][nt][2] + b0, acc[mt][nt][3] + b1);
            }
    }
}

// ---------------- fused edge GEMM (U, iU -> gmem; ee -> smem) + softmax + gather + Ux ----------------
// 160-row tiles = exactly 8 nodes. 640 threads, 5x4 warp grid, warp tile 32x32.
__global__ __launch_bounds__(640, 2)
void edge_fused_kernel(const float* __restrict__ A,
                       const __half* __restrict__ BU, const float* __restrict__ biasU, __half* __restrict__ outU,
                       const __half* __restrict__ BiU, const float* __restrict__ biasiU, __half* __restrict__ outiU,
                       const __half* __restrict__ Bee, const float* __restrict__ biasee,
                       const float2* __restrict__ Vx2, const float2* __restrict__ Ux2,
                       const int* __restrict__ edge_index,
                       float2* __restrict__ pps2, float2* __restrict__ ppq2)
{
    extern __shared__ __half sm[];
    __half* As = sm;                    // ETILE*TPAD; reused as Ve buffer at the end
    __half* Bs = sm + ETILE*TPAD;       // 128*TPAD
    __shared__ int sidx[ETILE];         // gather bases for this tile's 160 edges

    const int tid = threadIdx.x;
    const int row0 = blockIdx.x * ETILE;

    // gather bases: edge g = row0+t, b = g/Ee, base = (b*Nn + edge_index[g])*H2
    if (tid < ETILE) {
        int g = row0 + tid;
        int b = g / Ee;
        sidx[tid] = (b*Nn + edge_index[g]) * H2;
    }

    // A fill: 160x128 fp32 -> fp16 (5120 float4, 8 iters)
    {
        const float4* gA = (const float4*)A + (size_t)row0*32;
        #pragma unroll
        for (int i = 0; i < 8; ++i) {
            int idx = i*640 + tid;
            int r = idx >> 5, c = idx & 31;
            float4 v = gA[idx];
            __align__(8) __half h[4];
            h[0] = __float2half_rn(v.x); h[1] = __float2half_rn(v.y);
            h[2] = __float2half_rn(v.z); h[3] = __float2half_rn(v.w);
            *(uint2*)(As + r*TPAD + c*4) = *(const uint2*)h;
        }
    }

    const int warp = tid >> 5, lane = tid & 31;
    const int wr = warp >> 2;        // 0..4 : rows wr*32..+32
    const int wc = warp & 3;         // 0..3 : cols wc*32..+32
    const uint32_t a_sm = smem_u32(As), b_sm = smem_u32(Bs);
    const int a_row  = wr*32 + (lane & 15);
    const int a_koff = (lane >> 4) * 8;
    const int b_n    = wc*32 + (lane & 7) + ((lane >> 4) & 1)*8;
    const int b_koff = ((lane >> 3) & 1) * 8;
    const int gid = lane >> 2, tg = lane & 3;

    const __half* Bsrc[3] = {BU, BiU, Bee};
    const float* biases[3] = {biasU, biasiU, biasee};
    __half* outs[3] = {outU, outiU, (__half*)nullptr};

    #pragma unroll
    for (int w = 0; w < 3; ++w) {
        __syncthreads();
        {
            const uint4* gB = (const uint4*)Bsrc[w];
            #pragma unroll
            for (int i = 0; i < 4; ++i) {
                int idx = i*640 + tid;
                if (idx < 2048) {
                    int r = idx >> 4, c = idx & 15;
                    *(uint4*)(Bs + r*TPAD + c*8) = gB[idx];
                }
            }
        }
        __syncthreads();

        float acc[2][4][4];
        #pragma unroll
        for (int mt = 0; mt < 2; ++mt)
            #pragma unroll
            for (int nt = 0; nt < 4; ++nt)
                #pragma unroll
                for (int i = 0; i < 4; ++i) acc[mt][nt][i] = 0.f;

        #pragma unroll
        for (int ks = 0; ks < 8; ++ks) {
            const int k0 = ks * 16;
            uint32_t ah[2][4];
            #pragma unroll
            for (int mt = 0; mt < 2; ++mt)
                ldsm_x4(ah[mt], a_sm + (uint32_t)((a_row + mt*16)*TPAD + k0 + a_koff) * 2u);
            uint32_t bh[2][4];
            #pragma unroll
            for (int p = 0; p < 2; ++p)
                ldsm_x4(bh[p], b_sm + (uint32_t)((b_n + p*16)*TPAD + k0 + b_koff) * 2u);
            #pragma unroll
            for (int p = 0; p < 2; ++p)
                #pragma unroll
                for (int mt = 0; mt < 2; ++mt) {
                    mma_f16(acc[mt][2*p  ], ah[mt], bh[p]);
                    mma_f16(acc[mt][2*p+1], ah[mt], bh[p] + 2);
                }
        }

        const float* bias = biases[w];
        if (w < 2) {
            __half* out = outs[w];
            #pragma unroll
            for (int mt = 0; mt < 2; ++mt)
                #pragma unroll
                for (int nt = 0; nt < 4; ++nt) {
                    int col = wc*32 + nt*8 + tg*2;
                    float b0 = bias[col], b1 = bias[col+1];
                    size_t r0 = (size_t)row0 + wr*32 + mt*16 + gid;
                    *(__half2*)(out + r0*128 + col)     = __floats2half2_rn(acc[mt][nt][0] + b0, acc[mt][nt][1] + b1);
                    *(__half2*)(out + (r0+8)*128 + col) = __floats2half2_rn(acc[mt][nt][2] + b0, acc[mt][nt][3] + b1);
                }
        } else {
            // ee/Ve: stage into As (all warps done reading A after this sync)
            __syncthreads();
            #pragma unroll
            for (int mt = 0; mt < 2; ++mt)
                #pragma unroll
                for (int nt = 0; nt < 4; ++nt) {
                    int col = wc*32 + nt*8 + tg*2;
                    float b0 = bias[col], b1 = bias[col+1];
                    int rl = wr*32 + mt*16 + gid;
                    *(__half2*)(As + rl*TPAD + col)     = __floats2half2_rn(acc[mt][nt][0] + b0, acc[mt][nt][1] + b1);
                    *(__half2*)(As + (rl+8)*TPAD + col) = __floats2half2_rn(acc[mt][nt][2] + b0, acc[mt][nt][3] + b1);
                }
        }
    }
    __syncthreads();

    // ---- softmax + gather-aggregate + Ux add for the 8 nodes of this tile ----
    if (tid < 512) {
        const int local = tid >> 6;       // node 0..7
        const int h2 = tid & 63;
        const int bn = blockIdx.x*8 + local;
        const int* si = sidx + local*SFf;

        float ax = 0.f, ay = 0.f, dx = 0.f, dy = 0.f;
        #pragma unroll
        for (int s = 0; s < SFf; ++s) {
            float2 v = __half22float2(*(const __half2*)(As + (local*SFf + s)*TPAD + h2*2));
            float ex = __expf(v.x), ey = __expf(v.y);
            float2 vx = Vx2[si[s] + h2];
            dx += ex; dy += ey;
            ax += ex*vx.x; ay += ey*vx.y;
        }
        int o = bn*H2 + h2;
        float2 ux = Ux2[o];
        float2 val = make_float2(ux.x + ax/dx, ux.y + ay/dy);
        pps2[o] = val;                    // doubles as x_tmp
        ppq2[o] = make_float2(val.x*val.x, val.y*val.y);
    }
}

// ---------------- all weights: transpose to [n][k] fp16 ----------------
struct WPtrs { const float* w[7]; };
__global__ __launch_bounds__(128)
void wsplit_all_kernel(WPtrs wp, __half* __restrict__ wt)
{
    int wi = blockIdx.y, k = blockIdx.x, c = threadIdx.x;
    wt[(size_t)wi*16384 + c*128 + k] = __float2half_rn(wp.w[wi][k*128 + c]);
}

// ---------------- reduce per-(b,n) partials -> 256 partials (high-MLP) ----------------
__global__ __launch_bounds__(512)
void reduce_partials_kernel(const float4* __restrict__ ps4, const float4* __restrict__ pq4, int rows)
{
    __shared__ float4 ss[16][33], sq[16][33];
    const int c   = threadIdx.x & 31;
    const int sub = threadIdx.x >> 5;

    float4 s = make_float4(0.f,0.f,0.f,0.f);
    float4 q = make_float4(0.f,0.f,0.f,0.f);
    #pragma unroll 4
    for (int r = blockIdx.x*16 + sub; r < rows; r += gridDim.x*16) {
        float4 a = ps4[r*32 + c];
        float4 b = pq4[r*32 + c];
        s.x += a.x; s.y += a.y; s.z += a.z; s.w += a.w;
        q.x += b.x; q.y += b.y; q.z += b.z; q.w += b.w;
    }
    ss[sub][c] = s; sq[sub][c] = q;
    __syncthreads();

    if (sub == 0) {
        float4 ts = ss[0][c], tq = sq[0][c];
        #pragma unroll
        for (int i = 1; i < 16; ++i) {
            float4 a = ss[i][c], b = sq[i][c];
            ts.x += a.x; ts.y += a.y; ts.z += a.z; ts.w += a.w;
            tq.x += b.x; tq.y += b.y; tq.z += b.z; tq.w += b.w;
        }
        ((float4*)g_psum)[blockIdx.x*32 + c] = ts;
        ((float4*)g_psq )[blockIdx.x*32 + c] = tq;
    }
}

// ---------------- finalize mean / rstd ----------------
__global__ __launch_bounds__(Hh)
void finalize_stats_kernel(float inv_count)
{
    int h = threadIdx.x;
    float s = 0.f, q = 0.f;
    #pragma unroll 8
    for (int i = 0; i < STATS_BLOCKS; ++i) { s += g_psum[i*Hh + h]; q += g_psq[i*Hh + h]; }
    float mean = s * inv_count;
    float var  = q * inv_count - mean*mean;
    g_mean[h] = mean;
    g_rstd[h] = rsqrtf(var + BN_EPS);
}

// ---------------- BN apply + ReLU + residual, fp32 tmp (nodes) ----------------
__global__ __launch_bounds__(256)
void bn_apply_f32_kernel(const float* __restrict__ resid, const float* __restrict__ tmp,
                         const float* __restrict__ gamma, const float* __restrict__ beta,
                         float* __restrict__ out, int R)
{
    int total = R * 32;
    for (int idx = blockIdx.x*blockDim.x + threadIdx.x; idx < total;
         idx += gridDim.x*blockDim.x) {
        int h4 = (idx & 31) * 4;
        float4 t = ((const float4*)tmp)[idx];
        float4 r = ((const float4*)resid)[idx];
        float4 o;
        o.x = r.x + fmaxf((t.x - g_mean[h4  ]) * g_rstd[h4  ] * gamma[h4  ] + beta[h4  ], 0.f);
        o.y = r.y + fmaxf((t.y - g_mean[h4+1]) * g_rstd[h4+1] * gamma[h4+1] + beta[h4+1], 0.f);
        o.z = r.z + fmaxf((t.z - g_mean[h4+2]) * g_rstd[h4+2] * gamma[h4+2] + beta[h4+2], 0.f);
        o.w = r.w + fmaxf((t.w - g_mean[h4+3]) * g_rstd[h4+3] * gamma[h4+3] + beta[h4+3], 0.f);
        ((float4*)out)[idx] = o;
    }
}

// ---------------- BN apply + ReLU + residual, fp16 tmp (edges) ----------------
__global__ __launch_bounds__(256)
void bn_apply_f16_kernel(const float* __restrict__ resid, const __half* __restrict__ tmp,
                         const float* __restrict__ gamma, const float* __restrict__ beta,
                         float* __restrict__ out, int R)
{
    int total = R * 32;
    for (int idx = blockIdx.x*blockDim.x + threadIdx.x; idx < total;
         idx += gridDim.x*blockDim.x) {
        int h4 = (idx & 31) * 4;
        __half2 t01 = ((const __half2*)tmp)[2*idx];
        __half2 t23 = ((const __half2*)tmp)[2*idx + 1];
        float2 f01 = __half22float2(t01);
        float2 f23 = __half22float2(t23);
        float4 r = ((const float4*)resid)[idx];
        float4 o;
        o.x = r.x + fmaxf((f01.x - g_mean[h4  ]) * g_rstd[h4  ] * gamma[h4  ] + beta[h4  ], 0.f);
        o.y = r.y + fmaxf((f01.y - g_mean[h4+1]) * g_rstd[h4+1] * gamma[h4+1] + beta[h4+1], 0.f);
        o.z = r.z + fmaxf((f23.x - g_mean[h4+2]) * g_rstd[h4+2] * gamma[h4+2] + beta[h4+2], 0.f);
        o.w = r.w + fmaxf((f23.y - g_mean[h4+3]) * g_rstd[h4+3] * gamma[h4+3] + beta[h4+3], 0.f);
        ((float4*)out)[idx] = o;
    }
}

// ---------------- e_tmp = Ue + Vxt[gather] + Vxf + inv_emb (2 nodes/block, half2) ----------------
__global__ __launch_bounds__(128)
void etmp_kernel(const __half2* __restrict__ Ue2,  const __half2* __restrict__ iUe2,
                 const float2* __restrict__ Vxf2, const float2* __restrict__ Vxt2,
                 const float2* __restrict__ Wph2, const int* __restrict__ edge_index,
                 const int* __restrict__ inv_index, __half2* __restrict__ etmp2,
                 float2* __restrict__ pps2, float2* __restrict__ ppq2)
{
    const int local = threadIdx.x >> 6;
    const int h2 = threadIdx.x & 63;
    const int bn = blockIdx.x*2 + local;
    const int b = bn / Nn;

    __shared__ int sidx[2][SFf], sinv[2][SFf];
    if (h2 < SFf) {
        sidx[local][h2] = (b*Nn + edge_index[bn*SFf + h2]) * H2;
        int inv = inv_index[bn*SFf + h2];
        sinv[local][h2] = (inv < Ee) ? (b*Ee + inv) * H2 : -1;
    }
    __syncthreads();

    float2 vf = Vxf2[bn*H2 + h2];
    float2 wph = Wph2[h2];
    float sx = 0.f, sy = 0.f, qx = 0.f, qy = 0.f;
    const int* si = sidx[local];
    const int* sv = sinv[local];
    const int ebase = bn*SFf*H2 + h2;
    #pragma unroll
    for (int s = 0; s < SFf; ++s) {
        int eo = ebase + s*H2;
        int inv = sv[s];
        float2 ie = (inv >= 0) ? __half22float2(iUe2[inv + h2]) : wph;
        float2 ue = __half22float2(Ue2[eo]);
        float2 vt = Vxt2[si[s] + h2];
        float vx = ue.x + vt.x + vf.x + ie.x;
        float vy = ue.y + vt.y + vf.y + ie.y;
        etmp2[eo] = __floats2half2_rn(vx, vy);
        sx += vx; sy += vy; qx += vx*vx; qy += vy*vy;
    }
    int o = bn*H2 + h2;
    pps2[o] = make_float2(sx, sy);
    ppq2[o] = make_float2(qx, qy);
}

// ---------------- launch ----------------
extern "C" void kernel_launch(void* const* d_in, const int* in_sizes, int n_in,
                              void* d_out, int out_size)
{
    const float* x       = (const float*)d_in[0];
    const float* e       = (const float*)d_in[1];
    const int*   eidx    = (const int*)  d_in[2];
    const int*   inv_idx = (const int*)  d_in[3];
    const float* node_w  = (const float*)d_in[4];
    const float* node_b  = (const float*)d_in[5];
    const float* to_w    = (const float*)d_in[6];
    const float* to_b    = (const float*)d_in[7];
    const float* ee_w    = (const float*)d_in[8];
    const float* ee_b    = (const float*)d_in[9];
    const float* U_w     = (const float*)d_in[10];
    const float* U_b     = (const float*)d_in[11];
    const float* Vf_w    = (const float*)d_in[12];
    const float* Vf_b    = (const float*)d_in[13];
    const float* Vt_w    = (const float*)d_in[14];
    const float* Vt_b    = (const float*)d_in[15];
    const float* iU_w    = (const float*)d_in[16];
    const float* iU_b    = (const float*)d_in[17];
    const float* W_ph    = (const float*)d_in[18];
    const float* bnn_g   = (const float*)d_in[19];
    const float* bnn_b   = (const float*)d_in[20];
    const float* bne_g   = (const float*)d_in[21];
    const float* bne_b   = (const float*)d_in[22];

    float* out  = (float*)d_out;
    float* xnew = out;
    float* enew = out + (size_t)NODE_ROWS*Hh;

    float *pUx, *pVx, *pVxf, *pVxt, *pps, *ppq;
    __half *pe1, *pe2, *pe3;
    cudaGetSymbolAddress((void**)&pUx,  g_Ux);
    cudaGetSymbolAddress((void**)&pVx,  g_Vx);
    cudaGetSymbolAddress((void**)&pVxf, g_Vxf);
    cudaGetSymbolAddress((void**)&pVxt, g_Vxt);
    cudaGetSymbolAddress((void**)&pe1,  g_e1);
    cudaGetSymbolAddress((void**)&pe2,  g_e2);
    cudaGetSymbolAddress((void**)&pe3,  g_e3);
    cudaGetSymbolAddress((void**)&pps,  g_pps);
    cudaGetSymbolAddress((void**)&ppq,  g_ppq);

    __half* pwt;
    cudaGetSymbolAddress((void**)&pwt, g_wt);

    cudaFuncSetAttribute((const void*)&mma_gemm_node,    cudaFuncAttributeMaxDynamicSharedMemorySize, SM_GEMM);
    cudaFuncSetAttribute((const void*)&edge_fused_kernel, cudaFuncAttributeMaxDynamicSharedMemorySize, SM_EF);

    const int nodeBlocks = NODE_ROWS / 128;   // 125

    // weight order: 0=node,1=to,2=ee,3=U,4=iU,5=Vf,6=Vt
    WPtrs wp; wp.w[0]=node_w; wp.w[1]=to_w; wp.w[2]=ee_w; wp.w[3]=U_w; wp.w[4]=iU_w; wp.w[5]=Vf_w; wp.w[6]=Vt_w;
    wsplit_all_kernel<<<dim3(128,7), 128>>>(wp, pwt);

    // ---- NodeFeatures: x @ {node_w, to_w} (fp32 out) ----
    mma_gemm_node<<<nodeBlocks, 512, SM_GEMM>>>(x,
        pwt + 0*16384, node_b, pUx,
        pwt + 1*16384, to_b,   pVx);

    // ---- fused edge GEMM {U, iU -> gmem; ee -> smem} + softmax + gather + Ux ----
    edge_fused_kernel<<<EBLOCKS, 640, SM_EF>>>(e,
        pwt + 3*16384, U_b,  pe2,
        pwt + 4*16384, iU_b, pe3,
        pwt + 2*16384, ee_b,
        (const float2*)pVx, (const float2*)pUx, eidx,
        (float2*)pps, (float2*)ppq);

    reduce_partials_kernel<<<STATS_BLOCKS, 512>>>((const float4*)pps, (const float4*)ppq, Bb*Nn);
    finalize_stats_kernel<<<1, Hh>>>(1.0f / (float)NODE_ROWS);
    bn_apply_f32_kernel<<<1024, 256>>>(x, pps, bnn_g, bnn_b, xnew, NODE_ROWS);

    // ---- EdgeFeatures: xnew @ {Vf_w, Vt_w} (fp32 out) ----
    mma_gemm_node<<<nodeBlocks, 512, SM_GEMM>>>(xnew,
        pwt + 5*16384, Vf_b, pVxf,
        pwt + 6*16384, Vt_b, pVxt);

    etmp_kernel<<<Bb*Nn/2, 128>>>((const __half2*)pe2, (const __half2*)pe3,
        (const float2*)pVxf, (const float2*)pVxt, (const float2*)W_ph,
        eidx, inv_idx, (__half2*)pe1, (float2*)pps, (float2*)ppq);
    reduce_partials_kernel<<<STATS_BLOCKS, 512>>>((const float4*)pps, (const float4*)ppq, Bb*Nn);
    finalize_stats_kernel<<<1, Hh>>>(1.0f / (float)EDGE_ROWS);
    bn_apply_f16_kernel<<<4096, 256>>>(e, pe1, bne_g, bne_b, enew, EDGE_ROWS);
}

// round 16
// speedup vs baseline: 1.5360x; 1.5360x over previous
#include <cuda_runtime.h>
#include <cuda_bf16.h>
#include <cuda_fp16.h>
#include <cstdint>

// ---------------- problem constants ----------------
#define Hh   128
#define H2   64                  // half2 channel pairs
#define Bb   16
#define Nn   1000
#define SFf  20
#define Ee   20000
#define NODE_ROWS (Bb*Nn)        // 16000  = 125*128
#define EDGE_ROWS (Bb*Ee)        // 320000 = 2500*128
#define BN_EPS 1e-5f
#define STATS_BLOCKS 256

// smem tile geometry: 128 x 136 fp16 per buffer (pad 8 -> conflict-free ldmatrix)
#define TPAD 136
#define TBUF (128*TPAD)
#define SM_GEMM (2*TBUF*2)       // A + single B buffer = 69632 B -> 2 CTAs/SM

// ---------------- scratch (__device__ globals) ----------------
__device__ __half g_Ux [NODE_ROWS*Hh];
__device__ __half g_Vx [NODE_ROWS*Hh];
__device__ __half g_Vxf[NODE_ROWS*Hh];
__device__ __half g_Vxt[NODE_ROWS*Hh];
__device__ __half g_e1 [(size_t)EDGE_ROWS*Hh];   // Ve logits, then e_tmp
__device__ __half g_e2 [(size_t)EDGE_ROWS*Hh];   // Ue
__device__ __half g_e3 [(size_t)EDGE_ROWS*Hh];   // iUe
__device__ float g_psum[STATS_BLOCKS*Hh];
__device__ float g_psq [STATS_BLOCKS*Hh];
__device__ float g_mean[Hh];
__device__ float g_rstd[Hh];
__device__ float g_pps[(size_t)(Bb*Nn)*Hh];      // node: doubles as x_tmp
__device__ float g_ppq[(size_t)(Bb*Nn)*Hh];

__device__ __half g_wt[7][128*128];   // transposed [n][k], fp16

// ---------------- helpers ----------------
__device__ __forceinline__ uint32_t smem_u32(const void* p) {
    uint32_t a;
    asm("{ .reg .u64 t; cvta.to.shared.u64 t, %1; cvt.u32.u64 %0, t; }" : "=r"(a) : "l"(p));
    return a;
}
__device__ __forceinline__ void ldsm_x4(uint32_t* r, uint32_t addr) {
    asm volatile("ldmatrix.sync.aligned.m8n8.x4.shared.b16 {%0,%1,%2,%3}, [%4];"
                 : "=r"(r[0]), "=r"(r[1]), "=r"(r[2]), "=r"(r[3]) : "r"(addr));
}
__device__ __forceinline__ void mma_f16(float* c, const uint32_t* a, const uint32_t* b) {
    asm volatile("mma.sync.aligned.m16n8k16.row.col.f32.f16.f16.f32 "
                 "{%0,%1,%2,%3}, {%4,%5,%6,%7}, {%8,%9}, {%0,%1,%2,%3};"
                 : "+f"(c[0]), "+f"(c[1]), "+f"(c[2]), "+f"(c[3])
                 : "r"(a[0]), "r"(a[1]), "r"(a[2]), "r"(a[3]), "r"(b[0]), "r"(b[1]));
}

// ---------------- multi-weight GEMM, single B buffer refilled per weight ----------------
// smem = A tile + ONE B tile (70 KB) -> 2 CTAs/SM. fp16 outputs.
template<int NW>
__global__ __launch_bounds__(512)
void mma_gemm_multi(const float* __restrict__ A,
                    const __half* __restrict__ B0, const float* __restrict__ bias0, __half* __restrict__ out0,
                    const __half* __restrict__ B1, const float* __restrict__ bias1, __half* __restrict__ out1,
                    const __half* __restrict__ B2, const float* __restrict__ bias2, __half* __restrict__ out2)
{
    extern __shared__ __half sm[];
    __half* Bs = sm + TBUF;

    const int tid = threadIdx.x;
    const int row0 = blockIdx.x * 128;

    // ---- A tile: 128x128 fp32 -> fp16 ----
    {
        const float4* gA = (const float4*)A + (size_t)row0*32;
        #pragma unroll
        for (int i = 0; i < 8; ++i) {
            int idx = i*512 + tid;
            int r = idx >> 5, c = idx & 31;
            float4 v = gA[idx];
            __align__(8) __half h[4];
            h[0] = __float2half_rn(v.x); h[1] = __float2half_rn(v.y);
            h[2] = __float2half_rn(v.z); h[3] = __float2half_rn(v.w);
            *(uint2*)(sm + r*TPAD + c*4) = *(const uint2*)h;
        }
    }

    const int warp = tid >> 5, lane = tid & 31;
    const int wr = warp >> 2;        // rows wr*32..+32
    const int wc = warp & 3;         // cols wc*32..+32
    const uint32_t a_sm = smem_u32(sm);
    const uint32_t b_sm = smem_u32(Bs);
    const int a_row  = wr*32 + (lane & 15);
    const int a_koff = (lane >> 4) * 8;
    const int b_n    = wc*32 + (lane & 7) + ((lane >> 4) & 1)*8;
    const int b_koff = ((lane >> 3) & 1) * 8;
    const int gid = lane >> 2, tg = lane & 3;

    const __half* Bsrc[3] = {B0, B1, B2};
    const float* biases[3] = {bias0, bias1, bias2};
    __half* outs[3] = {out0, out1, out2};

    #pragma unroll
    for (int w = 0; w < NW; ++w) {
        __syncthreads();
        {
            const uint4* gB = (const uint4*)Bsrc[w];
            #pragma unroll
            for (int i = 0; i < 4; ++i) {
                int idx = i*512 + tid;
                int r = idx >> 4, c = idx & 15;
                *(uint4*)(Bs + r*TPAD + c*8) = gB[idx];
            }
        }
        __syncthreads();

        float acc[2][4][4];
        #pragma unroll
        for (int mt = 0; mt < 2; ++mt)
            #pragma unroll
            for (int nt = 0; nt < 4; ++nt)
                #pragma unroll
                for (int i = 0; i < 4; ++i) acc[mt][nt][i] = 0.f;

        #pragma unroll
        for (int ks = 0; ks < 8; ++ks) {
            const int k0 = ks * 16;
            uint32_t ah[2][4];
            #pragma unroll
            for (int mt = 0; mt < 2; ++mt)
                ldsm_x4(ah[mt], a_sm + (uint32_t)((a_row + mt*16)*TPAD + k0 + a_koff) * 2u);
            uint32_t bh[2][4];
            #pragma unroll
            for (int p = 0; p < 2; ++p)
                ldsm_x4(bh[p], b_sm + (uint32_t)((b_n + p*16)*TPAD + k0 + b_koff) * 2u);
            #pragma unroll
            for (int p = 0; p < 2; ++p)
                #pragma unroll
                for (int mt = 0; mt < 2; ++mt) {
                    mma_f16(acc[mt][2*p  ], ah[mt], bh[p]);
                    mma_f16(acc[mt][2*p+1], ah[mt], bh[p] + 2);
                }
        }

        const float* bias = biases[w];
        __half* out = outs[w];
        #pragma unroll
        for (int mt = 0; mt < 2; ++mt)
            #pragma unroll
            for (int nt = 0; nt < 4; ++nt) {
                int col = wc*32 + nt*8 + tg*2;
                float b0 = bias[col], b1 = bias[col+1];
                size_t r0 = (size_t)row0 + wr*32 + mt*16 + gid;
                *(__half2*)(out + r0*128 + col)     = __floats2half2_rn(acc[mt][nt][0] + b0, acc[mt][nt][1] + b1);
                *(__half2*)(out + (r0+8)*128 + col) = __floats2half2_rn(acc[mt][nt][2] + b0, acc[mt][nt][3] + b1);
            }
    }
}

// ---------------- all weights: transpose to [n][k] fp16 ----------------
struct WPtrs { const float* w[7]; };
__global__ __launch_bounds__(128)
void wsplit_all_kernel(WPtrs wp, __half* __restrict__ wt)
{
    int wi = blockIdx.y, k = blockIdx.x, c = threadIdx.x;
    wt[(size_t)wi*16384 + c*128 + k] = __float2half_rn(wp.w[wi][k*128 + c]);
}

// ---------------- softmax over SF + gather-agg + Ux add (single pass, shiftless) ----------------
// |Ve| <= ~4 so exp without max-shift is safe; mathematically identical.
__global__ __launch_bounds__(128)
void softmax_agg_kernel(const __half2* __restrict__ Ve2, const __half2* __restrict__ Vx2,
                        const __half2* __restrict__ Ux2, const int* __restrict__ edge_index,
                        float2* __restrict__ pps2, float2* __restrict__ ppq2)
{
    const int local = threadIdx.x >> 6;      // node within block: 0/1
    const int h2 = threadIdx.x & 63;         // channel pair 0..63
    const int bn = blockIdx.x*2 + local;
    const int b = bn / Nn;

    __shared__ int sidx[2][SFf];
    if (h2 < SFf)
        sidx[local][h2] = (b*Nn + edge_index[bn*SFf + h2]) * H2;
    __syncthreads();

    const __half2* vep = Ve2 + (size_t)bn*SFf*H2 + h2;
    const int* si = sidx[local];
    float ax = 0.f, ay = 0.f, dx = 0.f, dy = 0.f;
    #pragma unroll
    for (int s = 0; s < SFf; ++s) {
        float2 v = __half22float2(vep[s*H2]);
        float ex = __expf(v.x), ey = __expf(v.y);
        float2 vx = __half22float2(Vx2[si[s] + h2]);
        dx += ex; dy += ey;
        ax += ex*vx.x; ay += ey*vx.y;
    }
    int o = bn*H2 + h2;
    float2 ux = __half22float2(Ux2[o]);
    float2 val = make_float2(ux.x + ax/dx, ux.y + ay/dy);
    pps2[o] = val;                            // doubles as x_tmp
    ppq2[o] = make_float2(val.x*val.x, val.y*val.y);
}

// ---------------- reduce per-(b,n) partials -> 256 partials (high-MLP) ----------------
__global__ __launch_bounds__(512)
void reduce_partials_kernel(const float4* __restrict__ ps4, const float4* __restrict__ pq4, int rows)
{
    __shared__ float4 ss[16][33], sq[16][33];
    const int c   = threadIdx.x & 31;
    const int sub = threadIdx.x >> 5;

    float4 s = make_float4(0.f,0.f,0.f,0.f);
    float4 q = make_float4(0.f,0.f,0.f,0.f);
    #pragma unroll 4
    for (int r = blockIdx.x*16 + sub; r < rows; r += gridDim.x*16) {
        float4 a = ps4[r*32 + c];
        float4 b = pq4[r*32 + c];
        s.x += a.x; s.y += a.y; s.z += a.z; s.w += a.w;
        q.x += b.x; q.y += b.y; q.z += b.z; q.w += b.w;
    }
    ss[sub][c] = s; sq[sub][c] = q;
    __syncthreads();

    if (sub == 0) {
        float4 ts = ss[0][c], tq = sq[0][c];
        #pragma unroll
        for (int i = 1; i < 16; ++i) {
            float4 a = ss[i][c], b = sq[i][c];
            ts.x += a.x; ts.y += a.y; ts.z += a.z; ts.w += a.w;
            tq.x += b.x; tq.y += b.y; tq.z += b.z; tq.w += b.w;
        }
        ((float4*)g_psum)[blockIdx.x*32 + c] = ts;
        ((float4*)g_psq )[blockIdx.x*32 + c] = tq;
    }
}

// ---------------- finalize mean / rstd ----------------
__global__ __launch_bounds__(Hh)
void finalize_stats_kernel(float inv_count)
{
    int h = threadIdx.x;
    float s = 0.f, q = 0.f;
    #pragma unroll 8
    for (int i = 0; i < STATS_BLOCKS; ++i) { s += g_psum[i*Hh + h]; q += g_psq[i*Hh + h]; }
    float mean = s * inv_count;
    float var  = q * inv_count - mean*mean;
    g_mean[h] = mean;
    g_rstd[h] = rsqrtf(var + BN_EPS);
}

// ---------------- BN apply + ReLU + residual, fp32 tmp (nodes) ----------------
__global__ __launch_bounds__(256)
void bn_apply_f32_kernel(const float* __restrict__ resid, const float* __restrict__ tmp,
                         const float* __restrict__ gamma, const float* __restrict__ beta,
                         float* __restrict__ out, int R)
{
    int total = R * 32;
    for (int idx = blockIdx.x*blockDim.x + threadIdx.x; idx < total;
         idx += gridDim.x*blockDim.x) {
        int h4 = (idx & 31) * 4;
        float4 t = ((const float4*)tmp)[idx];
        float4 r = ((const float4*)resid)[idx];
        float4 o;
        o.x = r.x + fmaxf((t.x - g_mean[h4  ]) * g_rstd[h4  ] * gamma[h4  ] + beta[h4  ], 0.f);
        o.y = r.y + fmaxf((t.y - g_mean[h4+1]) * g_rstd[h4+1] * gamma[h4+1] + beta[h4+1], 0.f);
        o.z = r.z + fmaxf((t.z - g_mean[h4+2]) * g_rstd[h4+2] * gamma[h4+2] + beta[h4+2], 0.f);
        o.w = r.w + fmaxf((t.w - g_mean[h4+3]) * g_rstd[h4+3] * gamma[h4+3] + beta[h4+3], 0.f);
        ((float4*)out)[idx] = o;
    }
}

// ---------------- BN apply + ReLU + residual, fp16 tmp (edges) ----------------
__global__ __launch_bounds__(256)
void bn_apply_f16_kernel(const float* __restrict__ resid, const __half* __restrict__ tmp,
                         const float* __restrict__ gamma, const float* __restrict__ beta,
                         float* __restrict__ out, int R)
{
    int total = R * 32;
    for (int idx = blockIdx.x*blockDim.x + threadIdx.x; idx < total;
         idx += gridDim.x*blockDim.x) {
        int h4 = (idx & 31) * 4;
        __half2 t01 = ((const __half2*)tmp)[2*idx];
        __half2 t23 = ((const __half2*)tmp)[2*idx + 1];
        float2 f01 = __half22float2(t01);
        float2 f23 = __half22float2(t23);
        float4 r = ((const float4*)resid)[idx];
        float4 o;
        o.x = r.x + fmaxf((f01.x - g_mean[h4  ]) * g_rstd[h4  ] * gamma[h4  ] + beta[h4  ], 0.f);
        o.y = r.y + fmaxf((f01.y - g_mean[h4+1]) * g_rstd[h4+1] * gamma[h4+1] + beta[h4+1], 0.f);
        o.z = r.z + fmaxf((f23.x - g_mean[h4+2]) * g_rstd[h4+2] * gamma[h4+2] + beta[h4+2], 0.f);
        o.w = r.w + fmaxf((f23.y - g_mean[h4+3]) * g_rstd[h4+3] * gamma[h4+3] + beta[h4+3], 0.f);
        ((float4*)out)[idx] = o;
    }
}

// ---------------- e_tmp = Ue + Vxt[gather] + Vxf + inv_emb (2 nodes/block, half2) ----------------
__global__ __launch_bounds__(128)
void etmp_kernel(const __half2* __restrict__ Ue2,  const __half2* __restrict__ iUe2,
                 const __half2* __restrict__ Vxf2, const __half2* __restrict__ Vxt2,
                 const float2* __restrict__ Wph2, const int* __restrict__ edge_index,
                 const int* __restrict__ inv_index, __half2* __restrict__ etmp2,
                 float2* __restrict__ pps2, float2* __restrict__ ppq2)
{
    const int local = threadIdx.x >> 6;
    const int h2 = threadIdx.x & 63;
    const int bn = blockIdx.x*2 + local;
    const int b = bn / Nn;

    __shared__ int sidx[2][SFf], sinv[2][SFf];
    if (h2 < SFf) {
        sidx[local][h2] = (b*Nn + edge_index[bn*SFf + h2]) * H2;
        int inv = inv_index[bn*SFf + h2];
        sinv[local][h2] = (inv < Ee) ? (b*Ee + inv) * H2 : -1;
    }
    __syncthreads();

    float2 vf = __half22float2(Vxf2[bn*H2 + h2]);
    float2 wph = Wph2[h2];
    float sx = 0.f, sy = 0.f, qx = 0.f, qy = 0.f;
    const int* si = sidx[local];
    const int* sv = sinv[local];
    const int ebase = bn*SFf*H2 + h2;
    #pragma unroll
    for (int s = 0; s < SFf; ++s) {
        int eo = ebase + s*H2;
        int inv = sv[s];
        float2 ie = (inv >= 0) ? __half22float2(iUe2[inv + h2]) : wph;
        float2 ue = __half22float2(Ue2[eo]);
        float2 vt = __half22float2(Vxt2[si[s] + h2]);
        float vx = ue.x + vt.x + vf.x + ie.x;
        float vy = ue.y + vt.y + vf.y + ie.y;
        etmp2[eo] = __floats2half2_rn(vx, vy);
        sx += vx; sy += vy; qx += vx*vx; qy += vy*vy;
    }
    int o = bn*H2 + h2;
    pps2[o] = make_float2(sx, sy);
    ppq2[o] = make_float2(qx, qy);
}

// ---------------- launch ----------------
extern "C" void kernel_launch(void* const* d_in, const int* in_sizes, int n_in,
                              void* d_out, int out_size)
{
    const float* x       = (const float*)d_in[0];
    const float* e       = (const float*)d_in[1];
    const int*   eidx    = (const int*)  d_in[2];
    const int*   inv_idx = (const int*)  d_in[3];
    const float* node_w  = (const float*)d_in[4];
    const float* node_b  = (const float*)d_in[5];
    const float* to_w    = (const float*)d_in[6];
    const float* to_b    = (const float*)d_in[7];
    const float* ee_w    = (const float*)d_in[8];
    const float* ee_b    = (const float*)d_in[9];
    const float* U_w     = (const float*)d_in[10];
    const float* U_b     = (const float*)d_in[11];
    const float* Vf_w    = (const float*)d_in[12];
    const float* Vf_b    = (const float*)d_in[13];
    const float* Vt_w    = (const float*)d_in[14];
    const float* Vt_b    = (const float*)d_in[15];
    const float* iU_w    = (const float*)d_in[16];
    const float* iU_b    = (const float*)d_in[17];
    const float* W_ph    = (const float*)d_in[18];
    const float* bnn_g   = (const float*)d_in[19];
    const float* bnn_b   = (const float*)d_in[20];
    const float* bne_g   = (const float*)d_in[21];
    const float* bne_b   = (const float*)d_in[22];

    float* out  = (float*)d_out;
    float* xnew = out;
    float* enew = out + (size_t)NODE_ROWS*Hh;

    __half *pUx, *pVx, *pVxf, *pVxt, *pe1, *pe2, *pe3, *pwt;
    float *pps, *ppq;
    cudaGetSymbolAddress((void**)&pUx,  g_Ux);
    cudaGetSymbolAddress((void**)&pVx,  g_Vx);
    cudaGetSymbolAddress((void**)&pVxf, g_Vxf);
    cudaGetSymbolAddress((void**)&pVxt, g_Vxt);
    cudaGetSymbolAddress((void**)&pe1,  g_e1);
    cudaGetSymbolAddress((void**)&pe2,  g_e2);
    cudaGetSymbolAddress((void**)&pe3,  g_e3);
    cudaGetSymbolAddress((void**)&pps,  g_pps);
    cudaGetSymbolAddress((void**)&ppq,  g_ppq);
    cudaGetSymbolAddress((void**)&pwt,  g_wt);

    cudaFuncSetAttribute((const void*)&mma_gemm_multi<2>, cudaFuncAttributeMaxDynamicSharedMemorySize, SM_GEMM);
    cudaFuncSetAttribute((const void*)&mma_gemm_multi<3>, cudaFuncAttributeMaxDynamicSharedMemorySize, SM_GEMM);

    const int nodeBlocks = NODE_ROWS / 128;   // 125
    const int edgeBlocks = EDGE_ROWS / 128;   // 2500

    // weight order: 0=node,1=to,2=ee,3=U,4=iU,5=Vf,6=Vt
    WPtrs wp; wp.w[0]=node_w; wp.w[1]=to_w; wp.w[2]=ee_w; wp.w[3]=U_w; wp.w[4]=iU_w; wp.w[5]=Vf_w; wp.w[6]=Vt_w;
    wsplit_all_kernel<<<dim3(128,7), 128>>>(wp, pwt);

    // ---- NodeFeatures: x @ {node_w, to_w} (fp16 out) ----
    mma_gemm_multi<2><<<nodeBlocks, 512, SM_GEMM>>>(x,
        pwt + 0*16384, node_b, pUx,
        pwt + 1*16384, to_b,   pVx,
        (const __half*)nullptr, (const float*)nullptr, (__half*)nullptr);

    // ---- e @ {ee_w, U_w, iU_w}: single read of e, fp16 outputs, 2 CTAs/SM ----
    mma_gemm_multi<3><<<edgeBlocks, 512, SM_GEMM>>>(e,
        pwt + 2*16384, ee_b, pe1,
        pwt + 3*16384, U_b,  pe2,
        pwt + 4*16384, iU_b, pe3);

    softmax_agg_kernel<<<Bb*Nn/2, 128>>>((const __half2*)pe1, (const __half2*)pVx,
        (const __half2*)pUx, eidx, (float2*)pps, (float2*)ppq);
    reduce_partials_kernel<<<STATS_BLOCKS, 512>>>((const float4*)pps, (const float4*)ppq, Bb*Nn);
    finalize_stats_kernel<<<1, Hh>>>(1.0f / (float)NODE_ROWS);
    bn_apply_f32_kernel<<<1024, 256>>>(x, pps, bnn_g, bnn_b, xnew, NODE_ROWS);

    // ---- EdgeFeatures: xnew @ {Vf_w, Vt_w} (fp16 out) ----
    mma_gemm_multi<2><<<nodeBlocks, 512, SM_GEMM>>>(xnew,
        pwt + 5*16384, Vf_b, pVxf,
        pwt + 6*16384, Vt_b, pVxt,
        (const __half*)nullptr, (const float*)nullptr, (__half*)nullptr);

    etmp_kernel<<<Bb*Nn/2, 128>>>((const __half2*)pe2, (const __half2*)pe3,
        (const __half2*)pVxf, (const __half2*)pVxt, (const float2*)W_ph,
        eidx, inv_idx, (__half2*)pe1, (float2*)pps, (float2*)ppq);
    reduce_partials_kernel<<<STATS_BLOCKS, 512>>>((const float4*)pps, (const float4*)ppq, Bb*Nn);
    finalize_stats_kernel<<<1, Hh>>>(1.0f / (float)EDGE_ROWS);
    bn_apply_f16_kernel<<<4096, 256>>>(e, pe1, bne_g, bne_b, enew, EDGE_ROWS);
}

// round 17
// speedup vs baseline: 1.6315x; 1.0622x over previous
#include <cuda_runtime.h>
#include <cuda_bf16.h>
#include <cuda_fp16.h>
#include <cstdint>

// ---------------- problem constants ----------------
#define Hh   128
#define H2   64                  // half2 channel pairs
#define Bb   16
#define Nn   1000
#define SFf  20
#define Ee   20000
#define NODE_ROWS (Bb*Nn)        // 16000  = 125*128
#define EDGE_ROWS (Bb*Ee)        // 320000
#define BN_EPS 1e-5f
#define STATS_BLOCKS 256

// smem tile geometry (pad 8 -> conflict-free ldmatrix)
#define TPAD 136
#define TBUF (128*TPAD)
#define SM_GEMM (2*TBUF*2)           // node GEMM: A + single B = 69632 B -> 2 CTAs/SM
#define ETILE 160                    // edge tile rows = 8 nodes
#define EBLOCKS (EDGE_ROWS/ETILE)    // 2000
#define SM_EF ((ETILE+128)*TPAD*2)   // A/Ve buffer + B buffer = 78336 B

// ---------------- scratch (__device__ globals) ----------------
__device__ __half g_Ux [NODE_ROWS*Hh];
__device__ __half g_Vx [NODE_ROWS*Hh];
__device__ __half g_Vxf[NODE_ROWS*Hh];
__device__ __half g_Vxt[NODE_ROWS*Hh];
__device__ __half g_e1 [(size_t)EDGE_ROWS*Hh];   // e_tmp
__device__ __half g_e2 [(size_t)EDGE_ROWS*Hh];   // Ue
__device__ __half g_e3 [(size_t)EDGE_ROWS*Hh];   // iUe
__device__ float g_psum[STATS_BLOCKS*Hh];
__device__ float g_psq [STATS_BLOCKS*Hh];
__device__ float g_mean[Hh];
__device__ float g_rstd[Hh];
__device__ float g_pps[(size_t)(Bb*Nn)*Hh];      // node: doubles as x_tmp
__device__ float g_ppq[(size_t)(Bb*Nn)*Hh];

__device__ __half g_wt[7][128*128];   // transposed [n][k], fp16

// ---------------- helpers ----------------
__device__ __forceinline__ uint32_t smem_u32(const void* p) {
    uint32_t a;
    asm("{ .reg .u64 t; cvta.to.shared.u64 t, %1; cvt.u32.u64 %0, t; }" : "=r"(a) : "l"(p));
    return a;
}
__device__ __forceinline__ void ldsm_x4(uint32_t* r, uint32_t addr) {
    asm volatile("ldmatrix.sync.aligned.m8n8.x4.shared.b16 {%0,%1,%2,%3}, [%4];"
                 : "=r"(r[0]), "=r"(r[1]), "=r"(r[2]), "=r"(r[3]) : "r"(addr));
}
__device__ __forceinline__ void mma_f16(float* c, const uint32_t* a, const uint32_t* b) {
    asm volatile("mma.sync.aligned.m16n8k16.row.col.f32.f16.f16.f32 "
                 "{%0,%1,%2,%3}, {%4,%5,%6,%7}, {%8,%9}, {%0,%1,%2,%3};"
                 : "+f"(c[0]), "+f"(c[1]), "+f"(c[2]), "+f"(c[3])
                 : "r"(a[0]), "r"(a[1]), "r"(a[2]), "r"(a[3]), "r"(b[0]), "r"(b[1]));
}

// ---------------- node GEMM: 128-row tile, 2 weights, single B buffer, fp16 out ----------------
__global__ __launch_bounds__(512)
void mma_gemm_node(const float* __restrict__ A,
                   const __half* __restrict__ B0, const float* __restrict__ bias0, __half* __restrict__ out0,
                   const __half* __restrict__ B1, const float* __restrict__ bias1, __half* __restrict__ out1)
{
    extern __shared__ __half sm[];
    __half* Bs = sm + TBUF;
    const int tid = threadIdx.x;
    const int row0 = blockIdx.x * 128;

    {
        const float4* gA = (const float4*)A + (size_t)row0*32;
        #pragma unroll
        for (int i = 0; i < 8; ++i) {
            int idx = i*512 + tid;
            int r = idx >> 5, c = idx & 31;
            float4 v = gA[idx];
            __align__(8) __half h[4];
            h[0] = __float2half_rn(v.x); h[1] = __float2half_rn(v.y);
            h[2] = __float2half_rn(v.z); h[3] = __float2half_rn(v.w);
            *(uint2*)(sm + r*TPAD + c*4) = *(const uint2*)h;
        }
    }

    const int warp = tid >> 5, lane = tid & 31;
    const int wr = warp >> 2, wc = warp & 3;
    const uint32_t a_sm = smem_u32(sm), b_sm = smem_u32(Bs);
    const int a_row  = wr*32 + (lane & 15);
    const int a_koff = (lane >> 4) * 8;
    const int b_n    = wc*32 + (lane & 7) + ((lane >> 4) & 1)*8;
    const int b_koff = ((lane >> 3) & 1) * 8;
    const int gid = lane >> 2, tg = lane & 3;

    const __half* Bsrc[2] = {B0, B1};
    const float* biases[2] = {bias0, bias1};
    __half* outs[2] = {out0, out1};

    #pragma unroll
    for (int w = 0; w < 2; ++w) {
        __syncthreads();
        {
            const uint4* gB = (const uint4*)Bsrc[w];
            #pragma unroll
            for (int i = 0; i < 4; ++i) {
                int idx = i*512 + tid;
                int r = idx >> 4, c = idx & 15;
                *(uint4*)(Bs + r*TPAD + c*8) = gB[idx];
            }
        }
        __syncthreads();

        float acc[2][4][4];
        #pragma unroll
        for (int mt = 0; mt < 2; ++mt)
            #pragma unroll
            for (int nt = 0; nt < 4; ++nt)
                #pragma unroll
                for (int i = 0; i < 4; ++i) acc[mt][nt][i] = 0.f;

        #pragma unroll
        for (int ks = 0; ks < 8; ++ks) {
            const int k0 = ks * 16;
            uint32_t ah[2][4];
            #pragma unroll
            for (int mt = 0; mt < 2; ++mt)
                ldsm_x4(ah[mt], a_sm + (uint32_t)((a_row + mt*16)*TPAD + k0 + a_koff) * 2u);
            uint32_t bh[2][4];
            #pragma unroll
            for (int p = 0; p < 2; ++p)
                ldsm_x4(bh[p], b_sm + (uint32_t)((b_n + p*16)*TPAD + k0 + b_koff) * 2u);
            #pragma unroll
            for (int p = 0; p < 2; ++p)
                #pragma unroll
                for (int mt = 0; mt < 2; ++mt) {
                    mma_f16(acc[mt][2*p  ], ah[mt], bh[p]);
                    mma_f16(acc[mt][2*p+1], ah[mt], bh[p] + 2);
                }
        }

        const float* bias = biases[w];
        __half* out = outs[w];
        #pragma unroll
        for (int mt = 0; mt < 2; ++mt)
            #pragma unroll
            for (int nt = 0; nt < 4; ++nt) {
                int col = wc*32 + nt*8 + tg*2;
                float b0 = bias[col], b1 = bias[col+1];
                size_t r0 = (size_t)row0 + wr*32 + mt*16 + gid;
                *(__half2*)(out + r0*128 + col)     = __floats2half2_rn(acc[mt][nt][0] + b0, acc[mt][nt][1] + b1);
                *(__half2*)(out + (r0+8)*128 + col) = __floats2half2_rn(acc[mt][nt][2] + b0, acc[mt][nt][3] + b1);
            }
    }
}

// ---------------- fused edge GEMM (U, iU -> gmem; ee -> smem) + softmax + gather + Ux ----------------
// 160-row tiles = exactly 8 nodes. 640 threads, 5x4 warp grid, warp tile 32x32.
// NOTE: plain launch_bounds(640) (102-reg budget) — the (640,2) variant spilled accumulators.
__global__ __launch_bounds__(640)
void edge_fused_kernel(const float* __restrict__ A,
                       const __half* __restrict__ BU, const float* __restrict__ biasU, __half* __restrict__ outU,
                       const __half* __restrict__ BiU, const float* __restrict__ biasiU, __half* __restrict__ outiU,
                       const __half* __restrict__ Bee, const float* __restrict__ biasee,
                       const __half2* __restrict__ Vx2, const __half2* __restrict__ Ux2,
                       const int* __restrict__ edge_index,
                       float2* __restrict__ pps2, float2* __restrict__ ppq2)
{
    extern __shared__ __half sm[];
    __half* As = sm;                    // ETILE*TPAD; reused as Ve buffer at the end
    __half* Bs = sm + ETILE*TPAD;       // 128*TPAD
    __shared__ int sidx[ETILE];         // gather bases for this tile's 160 edges

    const int tid = threadIdx.x;
    const int row0 = blockIdx.x * ETILE;

    if (tid < ETILE) {
        int g = row0 + tid;
        int b = g / Ee;
        sidx[tid] = (b*Nn + edge_index[g]) * H2;
    }

    // A fill: 160x128 fp32 -> fp16 (5120 float4, 8 iters)
    {
        const float4* gA = (const float4*)A + (size_t)row0*32;
        #pragma unroll
        for (int i = 0; i < 8; ++i) {
            int idx = i*640 + tid;
            int r = idx >> 5, c = idx & 31;
            float4 v = gA[idx];
            __align__(8) __half h[4];
            h[0] = __float2half_rn(v.x); h[1] = __float2half_rn(v.y);
            h[2] = __float2half_rn(v.z); h[3] = __float2half_rn(v.w);
            *(uint2*)(As + r*TPAD + c*4) = *(const uint2*)h;
        }
    }

    const int warp = tid >> 5, lane = tid & 31;
    const int wr = warp >> 2;        // 0..4 : rows wr*32..+32
    const int wc = warp & 3;         // 0..3 : cols wc*32..+32
    const uint32_t a_sm = smem_u32(As), b_sm = smem_u32(Bs);
    const int a_row  = wr*32 + (lane & 15);
    const int a_koff = (lane >> 4) * 8;
    const int b_n    = wc*32 + (lane & 7) + ((lane >> 4) & 1)*8;
    const int b_koff = ((lane >> 3) & 1) * 8;
    const int gid = lane >> 2, tg = lane & 3;

    const __half* Bsrc[3] = {BU, BiU, Bee};
    const float* biases[3] = {biasU, biasiU, biasee};
    __half* outs[3] = {outU, outiU, (__half*)nullptr};

    #pragma unroll
    for (int w = 0; w < 3; ++w) {
        __syncthreads();
        {
            const uint4* gB = (const uint4*)Bsrc[w];
            #pragma unroll
            for (int i = 0; i < 4; ++i) {
                int idx = i*640 + tid;
                if (idx < 2048) {
                    int r = idx >> 4, c = idx & 15;
                    *(uint4*)(Bs + r*TPAD + c*8) = gB[idx];
                }
            }
        }
        __syncthreads();

        float acc[2][4][4];
        #pragma unroll
        for (int mt = 0; mt < 2; ++mt)
            #pragma unroll
            for (int nt = 0; nt < 4; ++nt)
                #pragma unroll
                for (int i = 0; i < 4; ++i) acc[mt][nt][i] = 0.f;

        #pragma unroll
        for (int ks = 0; ks < 8; ++ks) {
            const int k0 = ks * 16;
            uint32_t ah[2][4];
            #pragma unroll
            for (int mt = 0; mt < 2; ++mt)
                ldsm_x4(ah[mt], a_sm + (uint32_t)((a_row + mt*16)*TPAD + k0 + a_koff) * 2u);
            uint32_t bh[2][4];
            #pragma unroll
            for (int p = 0; p < 2; ++p)
                ldsm_x4(bh[p], b_sm + (uint32_t)((b_n + p*16)*TPAD + k0 + b_koff) * 2u);
            #pragma unroll
            for (int p = 0; p < 2; ++p)
                #pragma unroll
                for (int mt = 0; mt < 2; ++mt) {
                    mma_f16(acc[mt][2*p  ], ah[mt], bh[p]);
                    mma_f16(acc[mt][2*p+1], ah[mt], bh[p] + 2);
                }
        }

        const float* bias = biases[w];
        if (w < 2) {
            __half* out = outs[w];
            #pragma unroll
            for (int mt = 0; mt < 2; ++mt)
                #pragma unroll
                for (int nt = 0; nt < 4; ++nt) {
                    int col = wc*32 + nt*8 + tg*2;
                    float b0 = bias[col], b1 = bias[col+1];
                    size_t r0 = (size_t)row0 + wr*32 + mt*16 + gid;
                    *(__half2*)(out + r0*128 + col)     = __floats2half2_rn(acc[mt][nt][0] + b0, acc[mt][nt][1] + b1);
                    *(__half2*)(out + (r0+8)*128 + col) = __floats2half2_rn(acc[mt][nt][2] + b0, acc[mt][nt][3] + b1);
                }
        } else {
            // ee/Ve: stage into As (all warps done reading A after this sync)
            __syncthreads();
            #pragma unroll
            for (int mt = 0; mt < 2; ++mt)
                #pragma unroll
                for (int nt = 0; nt < 4; ++nt) {
                    int col = wc*32 + nt*8 + tg*2;
                    float b0 = bias[col], b1 = bias[col+1];
                    int rl = wr*32 + mt*16 + gid;
                    *(__half2*)(As + rl*TPAD + col)     = __floats2half2_rn(acc[mt][nt][0] + b0, acc[mt][nt][1] + b1);
                    *(__half2*)(As + (rl+8)*TPAD + col) = __floats2half2_rn(acc[mt][nt][2] + b0, acc[mt][nt][3] + b1);
                }
        }
    }
    __syncthreads();

    // ---- softmax + gather-aggregate + Ux add for the 8 nodes of this tile ----
    if (tid < 512) {
        const int local = tid >> 6;       // node 0..7
        const int h2 = tid & 63;
        const int bn = blockIdx.x*8 + local;
        const int* si = sidx + local*SFf;

        float ax = 0.f, ay = 0.f, dx = 0.f, dy = 0.f;
        #pragma unroll
        for (int s = 0; s < SFf; ++s) {
            float2 v = __half22float2(*(const __half2*)(As + (local*SFf + s)*TPAD + h2*2));
            float ex = __expf(v.x), ey = __expf(v.y);
            float2 vx = __half22float2(Vx2[si[s] + h2]);
            dx += ex; dy += ey;
            ax += ex*vx.x; ay += ey*vx.y;
        }
        int o = bn*H2 + h2;
        float2 ux = __half22float2(Ux2[o]);
        float2 val = make_float2(ux.x + ax/dx, ux.y + ay/dy);
        pps2[o] = val;                    // doubles as x_tmp
        ppq2[o] = make_float2(val.x*val.x, val.y*val.y);
    }
}

// ---------------- all weights: transpose to [n][k] fp16 ----------------
struct WPtrs { const float* w[7]; };
__global__ __launch_bounds__(128)
void wsplit_all_kernel(WPtrs wp, __half* __restrict__ wt)
{
    int wi = blockIdx.y, k = blockIdx.x, c = threadIdx.x;
    wt[(size_t)wi*16384 + c*128 + k] = __float2half_rn(wp.w[wi][k*128 + c]);
}

// ---------------- reduce per-(b,n) partials -> 256 partials (high-MLP) ----------------
__global__ __launch_bounds__(512)
void reduce_partials_kernel(const float4* __restrict__ ps4, const float4* __restrict__ pq4, int rows)
{
    __shared__ float4 ss[16][33], sq[16][33];
    const int c   = threadIdx.x & 31;
    const int sub = threadIdx.x >> 5;

    float4 s = make_float4(0.f,0.f,0.f,0.f);
    float4 q = make_float4(0.f,0.f,0.f,0.f);
    #pragma unroll 4
    for (int r = blockIdx.x*16 + sub; r < rows; r += gridDim.x*16) {
        float4 a = ps4[r*32 + c];
        float4 b = pq4[r*32 + c];
        s.x += a.x; s.y += a.y; s.z += a.z; s.w += a.w;
        q.x += b.x; q.y += b.y; q.z += b.z; q.w += b.w;
    }
    ss[sub][c] = s; sq[sub][c] = q;
    __syncthreads();

    if (sub == 0) {
        float4 ts = ss[0][c], tq = sq[0][c];
        #pragma unroll
        for (int i = 1; i < 16; ++i) {
            float4 a = ss[i][c], b = sq[i][c];
            ts.x += a.x; ts.y += a.y; ts.z += a.z; ts.w += a.w;
            tq.x += b.x; tq.y += b.y; tq.z += b.z; tq.w += b.w;
        }
        ((float4*)g_psum)[blockIdx.x*32 + c] = ts;
        ((float4*)g_psq )[blockIdx.x*32 + c] = tq;
    }
}

// ---------------- finalize mean / rstd ----------------
__global__ __launch_bounds__(Hh)
void finalize_stats_kernel(float inv_count)
{
    int h = threadIdx.x;
    float s = 0.f, q = 0.f;
    #pragma unroll 8
    for (int i = 0; i < STATS_BLOCKS; ++i) { s += g_psum[i*Hh + h]; q += g_psq[i*Hh + h]; }
    float mean = s * inv_count;
    float var  = q * inv_count - mean*mean;
    g_mean[h] = mean;
    g_rstd[h] = rsqrtf(var + BN_EPS);
}

// ---------------- BN apply + ReLU + residual, fp32 tmp (nodes) ----------------
__global__ __launch_bounds__(256)
void bn_apply_f32_kernel(const float* __restrict__ resid, const float* __restrict__ tmp,
                         const float* __restrict__ gamma, const float* __restrict__ beta,
                         float* __restrict__ out, int R)
{
    int total = R * 32;
    for (int idx = blockIdx.x*blockDim.x + threadIdx.x; idx < total;
         idx += gridDim.x*blockDim.x) {
        int h4 = (idx & 31) * 4;
        float4 t = ((const float4*)tmp)[idx];
        float4 r = ((const float4*)resid)[idx];
        float4 o;
        o.x = r.x + fmaxf((t.x - g_mean[h4  ]) * g_rstd[h4  ] * gamma[h4  ] + beta[h4  ], 0.f);
        o.y = r.y + fmaxf((t.y - g_mean[h4+1]) * g_rstd[h4+1] * gamma[h4+1] + beta[h4+1], 0.f);
        o.z = r.z + fmaxf((t.z - g_mean[h4+2]) * g_rstd[h4+2] * gamma[h4+2] + beta[h4+2], 0.f);
        o.w = r.w + fmaxf((t.w - g_mean[h4+3]) * g_rstd[h4+3] * gamma[h4+3] + beta[h4+3], 0.f);
        ((float4*)out)[idx] = o;
    }
}

// ---------------- BN apply + ReLU + residual, fp16 tmp (edges) ----------------
__global__ __launch_bounds__(256)
void bn_apply_f16_kernel(const float* __restrict__ resid, const __half* __restrict__ tmp,
                         const float* __restrict__ gamma, const float* __restrict__ beta,
                         float* __restrict__ out, int R)
{
    int total = R * 32;
    for (int idx = blockIdx.x*blockDim.x + threadIdx.x; idx < total;
         idx += gridDim.x*blockDim.x) {
        int h4 = (idx & 31) * 4;
        __half2 t01 = ((const __half2*)tmp)[2*idx];
        __half2 t23 = ((const __half2*)tmp)[2*idx + 1];
        float2 f01 = __half22float2(t01);
        float2 f23 = __half22float2(t23);
        float4 r = ((const float4*)resid)[idx];
        float4 o;
        o.x = r.x + fmaxf((f01.x - g_mean[h4  ]) * g_rstd[h4  ] * gamma[h4  ] + beta[h4  ], 0.f);
        o.y = r.y + fmaxf((f01.y - g_mean[h4+1]) * g_rstd[h4+1] * gamma[h4+1] + beta[h4+1], 0.f);
        o.z = r.z + fmaxf((f23.x - g_mean[h4+2]) * g_rstd[h4+2] * gamma[h4+2] + beta[h4+2], 0.f);
        o.w = r.w + fmaxf((f23.y - g_mean[h4+3]) * g_rstd[h4+3] * gamma[h4+3] + beta[h4+3], 0.f);
        ((float4*)out)[idx] = o;
    }
}

// ---------------- e_tmp = Ue + Vxt[gather] + Vxf + inv_emb (2 nodes/block, half2) ----------------
__global__ __launch_bounds__(128)
void etmp_kernel(const __half2* __restrict__ Ue2,  const __half2* __restrict__ iUe2,
                 const __half2* __restrict__ Vxf2, const __half2* __restrict__ Vxt2,
                 const float2* __restrict__ Wph2, const int* __restrict__ edge_index,
                 const int* __restrict__ inv_index, __half2* __restrict__ etmp2,
                 float2* __restrict__ pps2, float2* __restrict__ ppq2)
{
    const int local = threadIdx.x >> 6;
    const int h2 = threadIdx.x & 63;
    const int bn = blockIdx.x*2 + local;
    const int b = bn / Nn;

    __shared__ int sidx[2][SFf], sinv[2][SFf];
    if (h2 < SFf) {
        sidx[local][h2] = (b*Nn + edge_index[bn*SFf + h2]) * H2;
        int inv = inv_index[bn*SFf + h2];
        sinv[local][h2] = (inv < Ee) ? (b*Ee + inv) * H2 : -1;
    }
    __syncthreads();

    float2 vf = __half22float2(Vxf2[bn*H2 + h2]);
    float2 wph = Wph2[h2];
    float sx = 0.f, sy = 0.f, qx = 0.f, qy = 0.f;
    const int* si = sidx[local];
    const int* sv = sinv[local];
    const int ebase = bn*SFf*H2 + h2;
    #pragma unroll
    for (int s = 0; s < SFf; ++s) {
        int eo = ebase + s*H2;
        int inv = sv[s];
        float2 ie = (inv >= 0) ? __half22float2(iUe2[inv + h2]) : wph;
        float2 ue = __half22float2(Ue2[eo]);
        float2 vt = __half22float2(Vxt2[si[s] + h2]);
        float vx = ue.x + vt.x + vf.x + ie.x;
        float vy = ue.y + vt.y + vf.y + ie.y;
        etmp2[eo] = __floats2half2_rn(vx, vy);
        sx += vx; sy += vy; qx += vx*vx; qy += vy*vy;
    }
    int o = bn*H2 + h2;
    pps2[o] = make_float2(sx, sy);
    ppq2[o] = make_float2(qx, qy);
}

// ---------------- launch ----------------
extern "C" void kernel_launch(void* const* d_in, const int* in_sizes, int n_in,
                              void* d_out, int out_size)
{
    const float* x       = (const float*)d_in[0];
    const float* e       = (const float*)d_in[1];
    const int*   eidx    = (const int*)  d_in[2];
    const int*   inv_idx = (const int*)  d_in[3];
    const float* node_w  = (const float*)d_in[4];
    const float* node_b  = (const float*)d_in[5];
    const float* to_w    = (const float*)d_in[6];
    const float* to_b    = (const float*)d_in[7];
    const float* ee_w    = (const float*)d_in[8];
    const float* ee_b    = (const float*)d_in[9];
    const float* U_w     = (const float*)d_in[10];
    const float* U_b     = (const float*)d_in[11];
    const float* Vf_w    = (const float*)d_in[12];
    const float* Vf_b    = (const float*)d_in[13];
    const float* Vt_w    = (const float*)d_in[14];
    const float* Vt_b    = (const float*)d_in[15];
    const float* iU_w    = (const float*)d_in[16];
    const float* iU_b    = (const float*)d_in[17];
    const float* W_ph    = (const float*)d_in[18];
    const float* bnn_g   = (const float*)d_in[19];
    const float* bnn_b   = (const float*)d_in[20];
    const float* bne_g   = (const float*)d_in[21];
    const float* bne_b   = (const float*)d_in[22];

    float* out  = (float*)d_out;
    float* xnew = out;
    float* enew = out + (size_t)NODE_ROWS*Hh;

    __half *pUx, *pVx, *pVxf, *pVxt, *pe1, *pe2, *pe3, *pwt;
    float *pps, *ppq;
    cudaGetSymbolAddress((void**)&pUx,  g_Ux);
    cudaGetSymbolAddress((void**)&pVx,  g_Vx);
    cudaGetSymbolAddress((void**)&pVxf, g_Vxf);
    cudaGetSymbolAddress((void**)&pVxt, g_Vxt);
    cudaGetSymbolAddress((void**)&pe1,  g_e1);
    cudaGetSymbolAddress((void**)&pe2,  g_e2);
    cudaGetSymbolAddress((void**)&pe3,  g_e3);
    cudaGetSymbolAddress((void**)&pps,  g_pps);
    cudaGetSymbolAddress((void**)&ppq,  g_ppq);
    cudaGetSymbolAddress((void**)&pwt,  g_wt);

    cudaFuncSetAttribute((const void*)&mma_gemm_node,     cudaFuncAttributeMaxDynamicSharedMemorySize, SM_GEMM);
    cudaFuncSetAttribute((const void*)&edge_fused_kernel, cudaFuncAttributeMaxDynamicSharedMemorySize, SM_EF);

    const int nodeBlocks = NODE_ROWS / 128;   // 125

    // weight order: 0=node,1=to,2=ee,3=U,4=iU,5=Vf,6=Vt
    WPtrs wp; wp.w[0]=node_w; wp.w[1]=to_w; wp.w[2]=ee_w; wp.w[3]=U_w; wp.w[4]=iU_w; wp.w[5]=Vf_w; wp.w[6]=Vt_w;
    wsplit_all_kernel<<<dim3(128,7), 128>>>(wp, pwt);

    // ---- NodeFeatures: x @ {node_w, to_w} (fp16 out) ----
    mma_gemm_node<<<nodeBlocks, 512, SM_GEMM>>>(x,
        pwt + 0*16384, node_b, pUx,
        pwt + 1*16384, to_b,   pVx);

    // ---- fused edge GEMM {U, iU -> gmem; ee -> smem} + softmax + gather + Ux ----
    edge_fused_kernel<<<EBLOCKS, 640, SM_EF>>>(e,
        pwt + 3*16384, U_b,  pe2,
        pwt + 4*16384, iU_b, pe3,
        pwt + 2*16384, ee_b,
        (const __half2*)pVx, (const __half2*)pUx, eidx,
        (float2*)pps, (float2*)ppq);

    reduce_partials_kernel<<<STATS_BLOCKS, 512>>>((const float4*)pps, (const float4*)ppq, Bb*Nn);
    finalize_stats_kernel<<<1, Hh>>>(1.0f / (float)NODE_ROWS);
    bn_apply_f32_kernel<<<1024, 256>>>(x, pps, bnn_g, bnn_b, xnew, NODE_ROWS);

    // ---- EdgeFeatures: xnew @ {Vf_w, Vt_w} (fp16 out) ----
    mma_gemm_node<<<nodeBlocks, 512, SM_GEMM>>>(xnew,
        pwt + 5*16384, Vf_b, pVxf,
        pwt + 6*16384, Vt_b, pVxt);

    etmp_kernel<<<Bb*Nn/2, 128>>>((const __half2*)pe2, (const __half2*)pe3,
        (const __half2*)pVxf, (const __half2*)pVxt, (const float2*)W_ph,
        eidx, inv_idx, (__half2*)pe1, (float2*)pps, (float2*)ppq);
    reduce_partials_kernel<<<STATS_BLOCKS, 512>>>((const float4*)pps, (const float4*)ppq, Bb*Nn);
    finalize_stats_kernel<<<1, Hh>>>(1.0f / (float)EDGE_ROWS);
    bn_apply_f16_kernel<<<4096, 256>>>(e, pe1, bne_g, bne_b, enew, EDGE_ROWS);
}